// round 15
// baseline (speedup 1.0000x reference)
#include <cuda_runtime.h>
#include <cuda_bf16.h>
#include <math.h>

// Problem constants
#define Bsz     2
#define Npts    8192
#define Kn      3
#define NQ      (Bsz * Npts)
#define THREADS 128
#define WARPS   (THREADS / 32)     // 4 warps per block
#define G       4                  // queries per warp
#define QPB     (WARPS * G)        // 16 queries per block -> 1024 blocks
#define TILE_C  1024               // candidates per smem tile
#define NTILES  (Npts / TILE_C)    // 8 tiles
#define W       4                  // windows (32 cand each) per step -> 128/step

#define FULLMASK 0xffffffffu

// Precomputed candidate vectors {-2x, -2y, -2z, |s|^2}
__device__ float4 g_c4[NQ];

// Top-3 insert, strict < in ascending candidate order (= top_k tie-break).
// Rechecks f < t2, so stale ballot bits self-filter.
__device__ __forceinline__ void insert3(float f, int cand,
                                        float& t0, float& t1, float& t2,
                                        int& i0, int& i1, int& i2)
{
    if (f < t2) {
        if (f < t0)      { t2 = t1; i2 = i1; t1 = t0; i1 = i0; t0 = f; i0 = cand; }
        else if (f < t1) { t2 = t1; i2 = i1; t1 = f;  i1 = cand; }
        else             { t2 = f;  i2 = cand; }
    }
}

// Prep: build g_c4 and zero the output accumulator.
__global__ void prep_kernel(const float* __restrict__ xyz, float* __restrict__ out)
{
    const int t = blockIdx.x * blockDim.x + threadIdx.x;
    if (t == 0) out[0] = 0.0f;
    if (t >= NQ) return;
    const float x = xyz[t * 3 + 0];
    const float y = xyz[t * 3 + 1];
    const float z = xyz[t * 3 + 2];
    const float n = fmaf(x, x, fmaf(y, y, z * z));
    g_c4[t] = make_float4(-2.0f * x, -2.0f * y, -2.0f * z, n);
}

// Ballot-gated insert of a 32-candidate window for one query.
__device__ __forceinline__ void process_window(float tg, int cbase,
                                               float& t0, float& t1, float& t2,
                                               int& i0, int& i1, int& i2)
{
    unsigned bg = __ballot_sync(FULLMASK, tg < t2);
    while (bg) {
        const int l = __ffs(bg) - 1;
        bg &= bg - 1;
        const float tv = __shfl_sync(FULLMASK, tg, l);
        insert3(tv, cbase + l, t0, t1, t2, i0, i1, i2);
    }
}

// ---------------------------------------------------------------------------
// Fused KNN + loss (R14 structure, quad-width steps). Warp owns G=4 queries;
// lanes process 128 distinct candidates per step (4 float4 loads per lane).
// t-space: t = (-2s).q + |s|^2 = d - |q|^2, monotone per query.
// Slow path: per-query ballots over windows in ascending order; insert3
// rechecks -> exact sequential strict-< semantics (jax top_k tie-break).
// ---------------------------------------------------------------------------
__global__ __launch_bounds__(THREADS) void knnreg_kernel(
    const float* __restrict__ xyz,   // [B,N,3]
    const float* __restrict__ rot,   // [B,N,4]
    const float* __restrict__ scl,   // [B,N,3]
    const float* __restrict__ col,   // [B,N,45]
    const float* __restrict__ opa,   // [B,N,1]
    float* __restrict__ out)
{
    const int tid  = threadIdx.x;
    const int lane = tid & 31;
    const int wid  = tid >> 5;
    const int qblk = blockIdx.x * QPB;
    const int b    = qblk >> 13;                 // QPB=16 | 8192
    const float* xb = xyz + (size_t)b * Npts * 3;
    const float4* cb4 = g_c4 + (size_t)b * Npts;
    const int qw   = (qblk & (Npts - 1)) + wid * G;

    // Warp's queries (broadcast loads)
    float qx[G], qy[G], qz[G], qn[G];
    #pragma unroll
    for (int g = 0; g < G; g++) {
        const int q = qw + g;
        qx[g] = xb[q * 3 + 0];
        qy[g] = xb[q * 3 + 1];
        qz[g] = xb[q * 3 + 2];
        qn[g] = fmaf(qx[g], qx[g], fmaf(qy[g], qy[g], qz[g] * qz[g]));
    }

    float t0[G], t1[G], t2[G];
    int   i0[G], i1[G], i2[G];

    __shared__ float4 sc[TILE_C];
    __shared__ float  red[WARPS];

    // ---- stage tile 0 (LDG.128 -> STS.128) ----
    for (int k = tid; k < TILE_C; k += THREADS)
        sc[k] = cb4[k];
    __syncthreads();

    // ---- prologue: candidates 0..31 via warp lex-argmin (exact) ----
    {
        const float4 c = sc[lane];
        #pragma unroll
        for (int g = 0; g < G; g++) {
            float t = fmaf(qx[g], c.x, c.w);
            t = fmaf(qy[g], c.y, t);
            t = fmaf(qz[g], c.z, t);
            float v = t; int iv = lane;
            float rt[Kn]; int ri[Kn];
            #pragma unroll
            for (int r = 0; r < Kn; r++) {
                float bv = v; int bi = iv;
                #pragma unroll
                for (int off = 16; off > 0; off >>= 1) {
                    const float ov = __shfl_xor_sync(FULLMASK, bv, off);
                    const int   oo = __shfl_xor_sync(FULLMASK, bi, off);
                    if (ov < bv || (ov == bv && oo < bi)) { bv = ov; bi = oo; }
                }
                rt[r] = bv; ri[r] = bi;
                if (iv == bi) v = INFINITY;
            }
            t0[g] = rt[0]; t1[g] = rt[1]; t2[g] = rt[2];
            i0[g] = ri[0]; i1[g] = ri[1]; i2[g] = ri[2];
        }
    }

    // ---- candidates 32..127: three single-width steps (aligns loop to 128) ----
    #pragma unroll
    for (int pre = 1; pre < 4; pre++) {
        const int s = pre * 32;
        const float4 c = sc[s + lane];
        float tg[G];
        #pragma unroll
        for (int g = 0; g < G; g++) {
            float t = fmaf(qx[g], c.x, c.w);
            t = fmaf(qy[g], c.y, t);
            tg[g] = fmaf(qz[g], c.z, t);
        }
        const bool p = (tg[0] < t2[0]) | (tg[1] < t2[1])
                     | (tg[2] < t2[2]) | (tg[3] < t2[3]);
        if (__ballot_sync(FULLMASK, p)) {
            #pragma unroll
            for (int g = 0; g < G; g++)
                process_window(tg[g], s, t0[g], t1[g], t2[g], i0[g], i1[g], i2[g]);
        }
    }

    // ---- main scan: 128 candidates per step (W=4 windows) ----
    for (int tile = 0; tile < NTILES; tile++) {
        if (tile > 0) {
            __syncthreads();
            const int base = tile * TILE_C;
            for (int k = tid; k < TILE_C; k += THREADS)
                sc[k] = cb4[base + k];
            __syncthreads();
        }

        const int sbeg  = (tile == 0) ? 128 : 0;
        const int tbase = tile * TILE_C;
        for (int s = sbeg; s < TILE_C; s += 32 * W) {
            float4 c[W];
            #pragma unroll
            for (int w = 0; w < W; w++) c[w] = sc[s + w * 32 + lane];

            float tw[W][G];
            #pragma unroll
            for (int w = 0; w < W; w++) {
                #pragma unroll
                for (int g = 0; g < G; g++) {
                    float t = fmaf(qx[g], c[w].x, c[w].w);
                    t = fmaf(qy[g], c[w].y, t);
                    tw[w][g] = fmaf(qz[g], c[w].z, t);
                }
            }

            bool p = false;
            #pragma unroll
            for (int w = 0; w < W; w++)
                #pragma unroll
                for (int g = 0; g < G; g++)
                    p |= (tw[w][g] < t2[g]);

            if (__ballot_sync(FULLMASK, p)) {
                const int cbd = tbase + s;
                // windows in ascending candidate order; per query
                #pragma unroll
                for (int g = 0; g < G; g++) {
                    #pragma unroll
                    for (int w = 0; w < W; w++)
                        process_window(tw[w][g], cbd + w * 32,
                                       t0[g], t1[g], t2[g], i0[g], i1[g], i2[g]);
                }
            }
        }
    }

    // ---- fused loss phase ----
    float local = 0.0f;

    #pragma unroll
    for (int g = 0; g < G; g++) {
        if (lane == 0) {
            local += ((t0[g] + qn[g]) + (t1[g] + qn[g]) + (t2[g] + qn[g]))
                     * (1.0f / ((float)Bsz * Npts * Kn));
        }

        const int r0 = b * Npts + i0[g];
        const int r1 = b * Npts + i1[g];
        const int r2 = b * Npts + i2[g];

        // 53 channels: 0..3 rot(4), 4..6 scales(3), 7 opacity(1), 8..52 colors(45)
        for (int c = lane; c < 53; c += 32) {
            const float* bp; int C; int cc;
            if (c < 4)       { bp = rot; C = 4;  cc = c;     }
            else if (c < 7)  { bp = scl; C = 3;  cc = c - 4; }
            else if (c < 8)  { bp = opa; C = 1;  cc = 0;     }
            else             { bp = col; C = 45; cc = c - 8; }

            const float x0 = __ldg(bp + (size_t)r0 * C + cc);
            const float x1 = __ldg(bp + (size_t)r1 * C + cc);
            const float x2 = __ldg(bp + (size_t)r2 * C + cc);

            const float m  = (x0 + x1 + x2) * (1.0f / 3.0f);
            const float e0 = x0 - m, e1 = x1 - m, e2 = x2 - m;
            const float var = fmaf(e0, e0, fmaf(e1, e1, e2 * e2)) * 0.5f; // ddof=1
            local += sqrtf(var) * (1.0f / ((float)Bsz * Npts * (float)C));
        }
    }

    // warp reduce
    #pragma unroll
    for (int off = 16; off > 0; off >>= 1)
        local += __shfl_xor_sync(FULLMASK, local, off);

    __syncthreads();
    if (lane == 0) red[wid] = local;
    __syncthreads();

    if (tid == 0) {
        float s = 0.0f;
        #pragma unroll
        for (int w = 0; w < WARPS; w++) s += red[w];
        atomicAdd(out, s);
    }
}

// ---------------------------------------------------------------------------
extern "C" void kernel_launch(void* const* d_in, const int* in_sizes, int n_in,
                              void* d_out, int out_size)
{
    const float* xyz = (const float*)d_in[0];
    const float* rot = (const float*)d_in[1];
    const float* scl = (const float*)d_in[2];
    const float* col = (const float*)d_in[3];
    const float* opa = (const float*)d_in[4];
    float* out = (float*)d_out;

    prep_kernel<<<NQ / 256, 256>>>(xyz, out);
    knnreg_kernel<<<NQ / QPB, THREADS>>>(xyz, rot, scl, col, opa, out);
}